// round 1
// baseline (speedup 1.0000x reference)
#include <cuda_runtime.h>
#include <cuda_bf16.h>

#define NMAX   50000
#define HD     128
#define EMAX   800000
#define ELMAX  200000

// ---------------- device scratch (no allocations allowed) ----------------
__device__ float g_deg[NMAX];
__device__ float g_dinv[NMAX];
__device__ float g_Xh[(size_t)NMAX * HD];
__device__ float g_LX[(size_t)NMAX * HD];
__device__ float g_h [(size_t)NMAX * HD];
__device__ int   g_is64;

// ---------------- index-width detection ----------------
// edge_index is declared int64 in the reference, but JAX without x64 silently
// produces int32. Read the first 64 entries as int64: if the data is really
// int32, pairs of random indices combine to values >= N (prob of false
// positive ~ (1/N)^64 ~ 0). Reading 64*8 = 512B is within the buffer in
// either interpretation (buffer >= 6.4 MB).
__global__ void detect_kernel(const void* __restrict__ ei, int n_nodes) {
    const long long* p = (const long long*)ei;
    int ok64 = 1;
    for (int i = 0; i < 64; i++) {
        long long v = p[i];
        if (v < 0 || v >= (long long)n_nodes) { ok64 = 0; break; }
    }
    g_is64 = ok64;
}

__device__ __forceinline__ long long ld_idx(const void* p, long long i, int is64) {
    if (is64) return ((const long long*)p)[i];
    return (long long)((const int*)p)[i];
}

// ---------------- degree + dinv ----------------
__global__ void deg_kernel(const void* __restrict__ ei, int E) {
    int is64 = g_is64;
    for (int e = blockIdx.x * blockDim.x + threadIdx.x; e < E; e += gridDim.x * blockDim.x) {
        long long s = ld_idx(ei, e, is64);
        atomicAdd(&g_deg[s], 1.0f);
    }
}

__global__ void dinv_kernel(int n) {
    int i = blockIdx.x * blockDim.x + threadIdx.x;
    if (i < n) {
        float d = g_deg[i];
        g_dinv[i] = (d > 0.0f) ? rsqrtf(d) : 0.0f;
    }
}

// ---------------- pre GEMM: Xh = x @ pre_w + pre_b ----------------
// block: 256 threads, tile 64 rows x 128 cols, weights + x tile in smem.
__global__ void __launch_bounds__(256, 1)
gemm_pre_kernel(const float* __restrict__ x, const float* __restrict__ W,
                const float* __restrict__ bias, int n) {
    extern __shared__ float sm[];
    float* ws = sm;             // 128*128
    float* xs = sm + 128 * 128; // 64*128
    int t = threadIdx.x;
    int row0 = blockIdx.x * 64;

    { // load weight 16384 floats = 4096 float4
        const float4* W4 = (const float4*)W;
        float4* ws4 = (float4*)ws;
        #pragma unroll
        for (int i = 0; i < 16; i++) ws4[t + i * 256] = W4[t + i * 256];
    }
    { // load x tile: 64 rows * 32 float4 = 2048 float4
        const float4* x4 = (const float4*)x;
        float4* xs4 = (float4*)xs;
        #pragma unroll
        for (int i = 0; i < 8; i++) {
            int idx = t + i * 256;
            int r = idx >> 5;
            float4 v = make_float4(0.f, 0.f, 0.f, 0.f);
            if (row0 + r < n) v = x4[(size_t)(row0 + r) * 32 + (idx & 31)];
            xs4[idx] = v;
        }
    }
    __syncthreads();

    int ty = t >> 4, tx = t & 15;
    int rl = ty * 4, cl = tx * 8;
    float acc[4][8];
    #pragma unroll
    for (int i = 0; i < 4; i++)
        #pragma unroll
        for (int j = 0; j < 8; j++) acc[i][j] = 0.f;

    #pragma unroll 2
    for (int k = 0; k < 128; k += 4) {
        float4 a[4];
        #pragma unroll
        for (int i = 0; i < 4; i++) a[i] = *(const float4*)&xs[(rl + i) * 128 + k];
        #pragma unroll
        for (int kk = 0; kk < 4; kk++) {
            float4 b0 = *(const float4*)&ws[(k + kk) * 128 + cl];
            float4 b1 = *(const float4*)&ws[(k + kk) * 128 + cl + 4];
            #pragma unroll
            for (int i = 0; i < 4; i++) {
                float av = ((const float*)&a[i])[kk];
                acc[i][0] += av * b0.x; acc[i][1] += av * b0.y;
                acc[i][2] += av * b0.z; acc[i][3] += av * b0.w;
                acc[i][4] += av * b1.x; acc[i][5] += av * b1.y;
                acc[i][6] += av * b1.z; acc[i][7] += av * b1.w;
            }
        }
    }

    float4 bb0 = *(const float4*)&bias[cl];
    float4 bb1 = *(const float4*)&bias[cl + 4];
    #pragma unroll
    for (int i = 0; i < 4; i++) {
        int r = row0 + rl + i;
        if (r < n) {
            float4 o0 = make_float4(acc[i][0] + bb0.x, acc[i][1] + bb0.y,
                                    acc[i][2] + bb0.z, acc[i][3] + bb0.w);
            float4 o1 = make_float4(acc[i][4] + bb1.x, acc[i][5] + bb1.y,
                                    acc[i][6] + bb1.z, acc[i][7] + bb1.w);
            *(float4*)&g_Xh[(size_t)r * 128 + cl] = o0;
            *(float4*)&g_Xh[(size_t)r * 128 + cl + 4] = o1;
        }
    }
}

// ---------------- scatter: LX[dst] += -(dinv[s]*dinv[d]) * Xh[src] ----------------
// one warp per edge, float4 lanes, vector reduction atomics
__global__ void scatter_kernel(const void* __restrict__ ei, int E) {
    int is64 = g_is64;
    int gw = (blockIdx.x * blockDim.x + threadIdx.x) >> 5;
    int lane = threadIdx.x & 31;
    int nw = (gridDim.x * blockDim.x) >> 5;
    for (int e = gw; e < E; e += nw) {
        long long s = ld_idx(ei, e, is64);
        long long d = ld_idx(ei, (long long)E + e, is64);
        float w = -g_dinv[s] * g_dinv[d];
        if (w != 0.0f) {
            float4 v = ((const float4*)(g_Xh + (size_t)s * 128))[lane];
            float* dstp = (float*)(((float4*)(g_LX + (size_t)d * 128)) + lane);
            asm volatile("red.global.add.v4.f32 [%0], {%1, %2, %3, %4};"
                         :: "l"(dstp), "f"(w * v.x), "f"(w * v.y),
                            "f"(w * v.z), "f"(w * v.w)
                         : "memory");
        }
    }
}

// ---------------- fused gates ----------------
// h = relu( (1 - sigmoid(Xh@Wx00 + LX@Wx01 + bx0 + bh0))
//           * tanh   (Xh@Wx20 + LX@Wx21 + bx2 + bh2) )
__global__ void __launch_bounds__(256, 1)
gates_kernel(const float* __restrict__ Wx, const float* __restrict__ bx,
             const float* __restrict__ bh, int n) {
    extern __shared__ float sm[];
    float* wa = sm;           // 16384 floats
    float* wb = sm + 16384;   // 16384
    float* xs = sm + 32768;   // 8192
    float* ls = sm + 40960;   // 8192
    int t = threadIdx.x;
    int row0 = blockIdx.x * 64;
    int ty = t >> 4, tx = t & 15;
    int rl = ty * 4, cl = tx * 8;

    // load tiles (Xh, LX) — 2048 float4 each
    {
        float4* xs4 = (float4*)xs;
        float4* ls4 = (float4*)ls;
        const float4* X4 = (const float4*)g_Xh;
        const float4* L4 = (const float4*)g_LX;
        #pragma unroll
        for (int i = 0; i < 8; i++) {
            int idx = t + i * 256;
            int r = idx >> 5;
            float4 vx = make_float4(0.f, 0.f, 0.f, 0.f), vl = vx;
            if (row0 + r < n) {
                size_t off = (size_t)(row0 + r) * 32 + (idx & 31);
                vx = X4[off]; vl = L4[off];
            }
            xs4[idx] = vx; ls4[idx] = vl;
        }
    }
    // load z-gate weights: Wx[0][0], Wx[0][1]
    {
        const float4* A4 = (const float4*)(Wx);                 // offset 0
        const float4* B4 = (const float4*)(Wx + 16384);
        float4* wa4 = (float4*)wa; float4* wb4 = (float4*)wb;
        #pragma unroll
        for (int i = 0; i < 16; i++) {
            wa4[t + i * 256] = A4[t + i * 256];
            wb4[t + i * 256] = B4[t + i * 256];
        }
    }
    __syncthreads();

    float acc[4][8];
    #pragma unroll
    for (int i = 0; i < 4; i++)
        #pragma unroll
        for (int j = 0; j < 8; j++) acc[i][j] = 0.f;

    // pass 1: Zpre
    #pragma unroll 2
    for (int k = 0; k < 128; k += 4) {
        float4 a[4], c[4];
        #pragma unroll
        for (int i = 0; i < 4; i++) {
            a[i] = *(const float4*)&xs[(rl + i) * 128 + k];
            c[i] = *(const float4*)&ls[(rl + i) * 128 + k];
        }
        #pragma unroll
        for (int kk = 0; kk < 4; kk++) {
            float4 b0 = *(const float4*)&wa[(k + kk) * 128 + cl];
            float4 b1 = *(const float4*)&wa[(k + kk) * 128 + cl + 4];
            float4 d0 = *(const float4*)&wb[(k + kk) * 128 + cl];
            float4 d1 = *(const float4*)&wb[(k + kk) * 128 + cl + 4];
            #pragma unroll
            for (int i = 0; i < 4; i++) {
                float av = ((const float*)&a[i])[kk];
                float cv = ((const float*)&c[i])[kk];
                acc[i][0] += av * b0.x + cv * d0.x;
                acc[i][1] += av * b0.y + cv * d0.y;
                acc[i][2] += av * b0.z + cv * d0.z;
                acc[i][3] += av * b0.w + cv * d0.w;
                acc[i][4] += av * b1.x + cv * d1.x;
                acc[i][5] += av * b1.y + cv * d1.y;
                acc[i][6] += av * b1.z + cv * d1.z;
                acc[i][7] += av * b1.w + cv * d1.w;
            }
        }
    }

    // znr = 1 - sigmoid(zpre) = sigmoid(-zpre)
    float znr[4][8];
    {
        float bz[8];
        #pragma unroll
        for (int j = 0; j < 8; j++) bz[j] = bx[0 * 128 + cl + j] + bh[0 * 128 + cl + j];
        #pragma unroll
        for (int i = 0; i < 4; i++)
            #pragma unroll
            for (int j = 0; j < 8; j++) {
                float v = acc[i][j] + bz[j];
                znr[i][j] = 1.0f / (1.0f + __expf(v));
                acc[i][j] = 0.f;
            }
    }

    __syncthreads();  // everyone done reading wa/wb
    // load h-gate weights: Wx[2][0], Wx[2][1]
    {
        const float4* A4 = (const float4*)(Wx + 4 * 16384);
        const float4* B4 = (const float4*)(Wx + 5 * 16384);
        float4* wa4 = (float4*)wa; float4* wb4 = (float4*)wb;
        #pragma unroll
        for (int i = 0; i < 16; i++) {
            wa4[t + i * 256] = A4[t + i * 256];
            wb4[t + i * 256] = B4[t + i * 256];
        }
    }
    __syncthreads();

    // pass 2: Hpre
    #pragma unroll 2
    for (int k = 0; k < 128; k += 4) {
        float4 a[4], c[4];
        #pragma unroll
        for (int i = 0; i < 4; i++) {
            a[i] = *(const float4*)&xs[(rl + i) * 128 + k];
            c[i] = *(const float4*)&ls[(rl + i) * 128 + k];
        }
        #pragma unroll
        for (int kk = 0; kk < 4; kk++) {
            float4 b0 = *(const float4*)&wa[(k + kk) * 128 + cl];
            float4 b1 = *(const float4*)&wa[(k + kk) * 128 + cl + 4];
            float4 d0 = *(const float4*)&wb[(k + kk) * 128 + cl];
            float4 d1 = *(const float4*)&wb[(k + kk) * 128 + cl + 4];
            #pragma unroll
            for (int i = 0; i < 4; i++) {
                float av = ((const float*)&a[i])[kk];
                float cv = ((const float*)&c[i])[kk];
                acc[i][0] += av * b0.x + cv * d0.x;
                acc[i][1] += av * b0.y + cv * d0.y;
                acc[i][2] += av * b0.z + cv * d0.z;
                acc[i][3] += av * b0.w + cv * d0.w;
                acc[i][4] += av * b1.x + cv * d1.x;
                acc[i][5] += av * b1.y + cv * d1.y;
                acc[i][6] += av * b1.z + cv * d1.z;
                acc[i][7] += av * b1.w + cv * d1.w;
            }
        }
    }

    // h = relu(znr * tanh(hpre))
    {
        float bz[8];
        #pragma unroll
        for (int j = 0; j < 8; j++) bz[j] = bx[2 * 128 + cl + j] + bh[2 * 128 + cl + j];
        #pragma unroll
        for (int i = 0; i < 4; i++) {
            int r = row0 + rl + i;
            if (r < n) {
                float o[8];
                #pragma unroll
                for (int j = 0; j < 8; j++) {
                    float ht = tanhf(acc[i][j] + bz[j]);
                    float hc = znr[i][j] * ht;
                    o[j] = fmaxf(hc, 0.0f);
                }
                *(float4*)&g_h[(size_t)r * 128 + cl]     = make_float4(o[0], o[1], o[2], o[3]);
                *(float4*)&g_h[(size_t)r * 128 + cl + 4] = make_float4(o[4], o[5], o[6], o[7]);
            }
        }
    }
}

// ---------------- decoder: out[e] = dot(h[s]*h[d], pw) + pb ----------------
__global__ void decoder_kernel(const void* __restrict__ eli,
                               const float* __restrict__ post_w,
                               const float* __restrict__ post_b,
                               float* __restrict__ out, int EL) {
    int is64 = g_is64;
    int gw = (blockIdx.x * blockDim.x + threadIdx.x) >> 5;
    int lane = threadIdx.x & 31;
    int nw = (gridDim.x * blockDim.x) >> 5;
    // folded decoder weights for this lane's 4 features
    float4 w0 = ((const float4*)post_w)[lane * 2];
    float4 w1 = ((const float4*)post_w)[lane * 2 + 1];
    float pw0 = w0.x + w0.y, pw1 = w0.z + w0.w;
    float pw2 = w1.x + w1.y, pw3 = w1.z + w1.w;
    float pb = post_b[0] + post_b[1];
    for (int e = gw; e < EL; e += nw) {
        long long s = ld_idx(eli, e, is64);
        long long d = ld_idx(eli, (long long)EL + e, is64);
        float4 a = ((const float4*)(g_h + (size_t)s * 128))[lane];
        float4 b = ((const float4*)(g_h + (size_t)d * 128))[lane];
        float acc = a.x * b.x * pw0 + a.y * b.y * pw1 + a.z * b.z * pw2 + a.w * b.w * pw3;
        #pragma unroll
        for (int o = 16; o > 0; o >>= 1) acc += __shfl_xor_sync(0xFFFFFFFFu, acc, o);
        if (lane == 0) out[e] = acc + pb;
    }
}

// ---------------- launch ----------------
extern "C" void kernel_launch(void* const* d_in, const int* in_sizes, int n_in,
                              void* d_out, int out_size) {
    const float* x      = (const float*)d_in[0];
    const void*  ei     = d_in[1];
    const void*  eli    = d_in[2];
    const float* pre_w  = (const float*)d_in[3];
    const float* pre_b  = (const float*)d_in[4];
    const float* Wx     = (const float*)d_in[5];
    const float* bx     = (const float*)d_in[6];
    const float* Wh     = (const float*)d_in[7];  (void)Wh;  // H0=0 -> only biases matter
    const float* bh     = (const float*)d_in[8];
    const float* post_w = (const float*)d_in[9];
    const float* post_b = (const float*)d_in[10];
    float* out = (float*)d_out;

    int N  = in_sizes[0] / HD;
    int E  = in_sizes[1] / 2;
    int EL = in_sizes[2] / 2;

    void *p_deg = nullptr, *p_LX = nullptr;
    cudaGetSymbolAddress(&p_deg, g_deg);
    cudaGetSymbolAddress(&p_LX, g_LX);
    cudaMemsetAsync(p_deg, 0, (size_t)N * sizeof(float));
    cudaMemsetAsync(p_LX, 0, (size_t)N * HD * sizeof(float));

    detect_kernel<<<1, 1>>>(ei, N);
    deg_kernel<<<1024, 256>>>(ei, E);
    dinv_kernel<<<(N + 255) / 256, 256>>>(N);

    cudaFuncSetAttribute(gemm_pre_kernel,
                         cudaFuncAttributeMaxDynamicSharedMemorySize, 96 * 1024);
    gemm_pre_kernel<<<(N + 63) / 64, 256, 96 * 1024>>>(x, pre_w, pre_b, N);

    scatter_kernel<<<(E + 7) / 8, 256>>>(ei, E);

    cudaFuncSetAttribute(gates_kernel,
                         cudaFuncAttributeMaxDynamicSharedMemorySize, 192 * 1024);
    gates_kernel<<<(N + 63) / 64, 256, 192 * 1024>>>(Wx, bx, bh, N);

    decoder_kernel<<<(EL + 7) / 8, 256>>>(eli, post_w, post_b, out, EL);
}

// round 2
// speedup vs baseline: 1.7361x; 1.7361x over previous
#include <cuda_runtime.h>
#include <cuda_bf16.h>
#include <mma.h>

using namespace nvcuda;

#define NMAX    50000
#define NPADMAX 50176   // ceil(50000/128)*128
#define HD      128
#define EMAX    800000
#define ELMAX   200000

// ---------------- device scratch (no allocations allowed) ----------------
__device__ int   g_degs[NMAX];      // out-degree (node as src) for dinv
__device__ int   g_cnt[NMAX];       // in-count (node as dst) for CSR
__device__ int   g_fill[NMAX];      // CSR fill cursors
__device__ int   g_rowptr[NMAX + 1];
__device__ int   g_col[EMAX];       // CSR: src indices grouped by dst
__device__ float g_dinv[NMAX];
__device__ float g_Xh[(size_t)NPADMAX * HD];
__device__ float g_LX[(size_t)NPADMAX * HD];
__device__ float g_h [(size_t)NPADMAX * HD];
__device__ int   g_is64;

// ---------------- index-width detection ----------------
// edge_index is int64 in the reference, but JAX without x64 silently yields
// int32. Interpret the first 64 entries as int64: random int32 pairs combine
// to values >= N with overwhelming probability, so 64 in-range int64 reads
// uniquely identify true int64 data.
__global__ void detect_kernel(const void* __restrict__ ei, int n_nodes) {
    const long long* p = (const long long*)ei;
    int ok64 = 1;
    for (int i = 0; i < 64; i++) {
        long long v = p[i];
        if (v < 0 || v >= (long long)n_nodes) { ok64 = 0; break; }
    }
    g_is64 = ok64;
}

__device__ __forceinline__ long long ld_idx(const void* p, long long i, int is64) {
    if (is64) return ((const long long*)p)[i];
    return (long long)((const int*)p)[i];
}

// ---------------- histogram: out-degree (src) + in-count (dst) ----------------
__global__ void hist_kernel(const void* __restrict__ ei, int E) {
    int is64 = g_is64;
    for (int e = blockIdx.x * blockDim.x + threadIdx.x; e < E; e += gridDim.x * blockDim.x) {
        long long s = ld_idx(ei, e, is64);
        long long d = ld_idx(ei, (long long)E + e, is64);
        atomicAdd(&g_degs[s], 1);
        atomicAdd(&g_cnt[d], 1);
    }
}

__global__ void dinv_kernel(int n) {
    int i = blockIdx.x * blockDim.x + threadIdx.x;
    if (i < n) {
        int d = g_degs[i];
        g_dinv[i] = (d > 0) ? rsqrtf((float)d) : 0.0f;
    }
}

// ---------------- exclusive scan of g_cnt -> g_rowptr (single block) ----------------
__global__ void scan_kernel(int n) {
    __shared__ int warpsum[32];
    __shared__ int carry_sm;
    int t = threadIdx.x;
    int lane = t & 31, wid = t >> 5;
    if (t == 0) { carry_sm = 0; g_rowptr[0] = 0; }
    __syncthreads();
    for (int base = 0; base < n; base += 1024) {
        int i = base + t;
        int x = (i < n) ? g_cnt[i] : 0;
        // inclusive warp scan
        #pragma unroll
        for (int off = 1; off < 32; off <<= 1) {
            int u = __shfl_up_sync(0xFFFFFFFFu, x, off);
            if (lane >= off) x += u;
        }
        if (lane == 31) warpsum[wid] = x;
        __syncthreads();
        if (wid == 0) {
            int s = warpsum[lane];
            #pragma unroll
            for (int off = 1; off < 32; off <<= 1) {
                int u = __shfl_up_sync(0xFFFFFFFFu, s, off);
                if (lane >= off) s += u;
            }
            warpsum[lane] = s;
        }
        __syncthreads();
        int add = (wid > 0) ? warpsum[wid - 1] : 0;
        int c = carry_sm;
        if (i < n) g_rowptr[i + 1] = c + add + x;
        __syncthreads();
        if (t == 0) carry_sm = c + warpsum[31];
        __syncthreads();
    }
}

// ---------------- CSR fill: group src indices by dst ----------------
__global__ void fill_kernel(const void* __restrict__ ei, int E) {
    int is64 = g_is64;
    for (int e = blockIdx.x * blockDim.x + threadIdx.x; e < E; e += gridDim.x * blockDim.x) {
        long long s = ld_idx(ei, e, is64);
        long long d = ld_idx(ei, (long long)E + e, is64);
        int pos = g_rowptr[d] + atomicAdd(&g_fill[d], 1);
        g_col[pos] = (int)s;
    }
}

// ---------------- SpMM: LX[d] = sum_{e: dst=d} -(dinv[s]*dinv[d]) * Xh[s] ------
// one warp per dst row, no atomics, full overwrite (padded rows get zeros)
__global__ void spmm_kernel(int n, int npad) {
    int gw = (blockIdx.x * blockDim.x + threadIdx.x) >> 5;
    int lane = threadIdx.x & 31;
    if (gw >= npad) return;
    float4 acc = make_float4(0.f, 0.f, 0.f, 0.f);
    if (gw < n) {
        int beg = g_rowptr[gw], end = g_rowptr[gw + 1];
        float dv = -g_dinv[gw];
        const float4* X4 = (const float4*)g_Xh;
        for (int j = beg; j < end; j++) {
            int s = g_col[j];
            float w = dv * g_dinv[s];
            float4 v = X4[(size_t)s * 32 + lane];
            acc.x += w * v.x; acc.y += w * v.y;
            acc.z += w * v.z; acc.w += w * v.w;
        }
    }
    ((float4*)g_LX)[(size_t)gw * 32 + lane] = acc;
}

// ---------------- tf32 tensor-core GEMM: Xh = x @ pre_w + pre_b ----------------
// block = 128 rows x 128 cols, 8 warps; A, B, bias tiles in smem
__global__ void __launch_bounds__(256)
gemm_pre_tc(const float* __restrict__ x, const float* __restrict__ W,
            const float* __restrict__ bias, int n) {
    extern __shared__ float sm[];
    float* As   = sm;                  // 128 x 136
    float* Bs   = sm + 17408;          // 128 x 136
    float* Bias = sm + 34816;          // 16 x 136
    int t = threadIdx.x;
    int row0 = blockIdx.x * 128;

    const float4* x4 = (const float4*)x;
    #pragma unroll
    for (int i = 0; i < 16; i++) {
        int idx = t + i * 256;
        int r = idx >> 5, c = idx & 31;
        float4 v = make_float4(0.f, 0.f, 0.f, 0.f);
        if (row0 + r < n) v = x4[(size_t)(row0 + r) * 32 + c];
        *(float4*)&As[r * 136 + c * 4] = v;
    }
    const float4* W4 = (const float4*)W;
    #pragma unroll
    for (int i = 0; i < 16; i++) {
        int idx = t + i * 256;
        int r = idx >> 5, c = idx & 31;
        *(float4*)&Bs[r * 136 + c * 4] = W4[idx];
    }
    #pragma unroll
    for (int i = 0; i < 8; i++) {
        int idx = t + i * 256;      // 0..2047
        int r = idx >> 7, c = idx & 127;
        Bias[r * 136 + c] = bias[c];
    }
    __syncthreads();

    int warp = t >> 5;
    int wr = warp & 3;   // 32-row group
    int wc = warp >> 2;  // 64-col group

    wmma::fragment<wmma::accumulator, 16, 16, 8, float> acc[2][4];
    #pragma unroll
    for (int i = 0; i < 2; i++)
        #pragma unroll
        for (int j = 0; j < 4; j++)
            wmma::load_matrix_sync(acc[i][j], &Bias[wc * 64 + j * 16], 136,
                                   wmma::mem_row_major);

    for (int k = 0; k < 128; k += 8) {
        wmma::fragment<wmma::matrix_a, 16, 16, 8, wmma::precision::tf32, wmma::row_major> af[2];
        wmma::fragment<wmma::matrix_b, 16, 16, 8, wmma::precision::tf32, wmma::row_major> bf[4];
        #pragma unroll
        for (int i = 0; i < 2; i++) {
            wmma::load_matrix_sync(af[i], &As[(wr * 32 + i * 16) * 136 + k], 136);
            #pragma unroll
            for (int e = 0; e < af[i].num_elements; e++)
                af[i].x[e] = wmma::__float_to_tf32(af[i].x[e]);
        }
        #pragma unroll
        for (int j = 0; j < 4; j++) {
            wmma::load_matrix_sync(bf[j], &Bs[k * 136 + wc * 64 + j * 16], 136);
            #pragma unroll
            for (int e = 0; e < bf[j].num_elements; e++)
                bf[j].x[e] = wmma::__float_to_tf32(bf[j].x[e]);
        }
        #pragma unroll
        for (int i = 0; i < 2; i++)
            #pragma unroll
            for (int j = 0; j < 4; j++)
                wmma::mma_sync(acc[i][j], af[i], bf[j], acc[i][j]);
    }

    #pragma unroll
    for (int i = 0; i < 2; i++)
        #pragma unroll
        for (int j = 0; j < 4; j++)
            wmma::store_matrix_sync(
                &g_Xh[(size_t)(row0 + wr * 32 + i * 16) * 128 + wc * 64 + j * 16],
                acc[i][j], 128, wmma::mem_row_major);
}

// ---------------- fused gates (tf32 tensor cores) ----------------
// h = relu( sigmoid(-(Xh@Wx00 + LX@Wx01 + bx0 + bh0))
//           * tanh (Xh@Wx20 + LX@Wx21 + bx2 + bh2) )
// A = [Xh | LX] (K=256) stays resident in smem; B streamed per gate in two
// 128-row chunks; gate-z result (1-Z) kept in accumulator registers.
__global__ void __launch_bounds__(256)
gates_tc(const float* __restrict__ Wx, const float* __restrict__ bx,
         const float* __restrict__ bh) {
    extern __shared__ float sm[];
    float* As   = sm;                   // 128 x 264 = 33792
    float* Bs   = sm + 33792;           // 128 x 136 = 17408
    float* Bias = sm + 33792 + 17408;   // 16 x 136
    int t = threadIdx.x;
    int row0 = blockIdx.x * 128;

    // load A tile: 128 rows x 256 cols (Xh | LX); grid covers padded rows only
    #pragma unroll
    for (int i = 0; i < 32; i++) {
        int idx = t + i * 256;          // 0..8191 float4 slots
        int r = idx >> 6, c = idx & 63; // c in float4 units over 256 floats
        const float4* src4 = (c < 32) ? (const float4*)g_Xh : (const float4*)g_LX;
        float4 v = src4[(size_t)(row0 + r) * 32 + (c & 31)];
        *(float4*)&As[r * 264 + c * 4] = v;
    }

    int warp = t >> 5;
    int wr = warp & 3;
    int wc = warp >> 2;

    wmma::fragment<wmma::accumulator, 16, 16, 8, float> acc_z[2][4];
    wmma::fragment<wmma::accumulator, 16, 16, 8, float> acc_h[2][4];

    #pragma unroll
    for (int g = 0; g < 2; g++) {
        int g3 = (g == 0) ? 0 : 2;          // gate index in Wx/bx/bh
        int wbase = g3 * 2;                 // 16384-float block offset in Wx

        __syncthreads();   // protect Bias/Bs from previous use
        // bias tile: bx[g3] + bh[g3], replicated over 16 rows
        #pragma unroll
        for (int i = 0; i < 8; i++) {
            int idx = t + i * 256;
            int r = idx >> 7, c = idx & 127;
            Bias[r * 136 + c] = bx[g3 * 128 + c] + bh[g3 * 128 + c];
        }
        // B chunk 0: k rows [0,128) = Wx[g3][0]
        const float4* B4 = (const float4*)(Wx + (size_t)wbase * 16384);
        #pragma unroll
        for (int i = 0; i < 16; i++) {
            int idx = t + i * 256;
            int r = idx >> 5, c = idx & 31;
            *(float4*)&Bs[r * 136 + c * 4] = B4[idx];
        }
        __syncthreads();

        #pragma unroll
        for (int i = 0; i < 2; i++)
            #pragma unroll
            for (int j = 0; j < 4; j++) {
                if (g == 0)
                    wmma::load_matrix_sync(acc_z[i][j], &Bias[wc * 64 + j * 16], 136,
                                           wmma::mem_row_major);
                else
                    wmma::load_matrix_sync(acc_h[i][j], &Bias[wc * 64 + j * 16], 136,
                                           wmma::mem_row_major);
            }

        #pragma unroll
        for (int c2 = 0; c2 < 2; c2++) {
            if (c2 == 1) {
                __syncthreads();
                const float4* B4b = (const float4*)(Wx + (size_t)(wbase + 1) * 16384);
                #pragma unroll
                for (int i = 0; i < 16; i++) {
                    int idx = t + i * 256;
                    int r = idx >> 5, c = idx & 31;
                    *(float4*)&Bs[r * 136 + c * 4] = B4b[idx];
                }
                __syncthreads();
            }
            for (int k = 0; k < 128; k += 8) {
                wmma::fragment<wmma::matrix_a, 16, 16, 8, wmma::precision::tf32, wmma::row_major> af[2];
                wmma::fragment<wmma::matrix_b, 16, 16, 8, wmma::precision::tf32, wmma::row_major> bf[4];
                #pragma unroll
                for (int i = 0; i < 2; i++) {
                    wmma::load_matrix_sync(af[i], &As[(wr * 32 + i * 16) * 264 + c2 * 128 + k], 264);
                    #pragma unroll
                    for (int e = 0; e < af[i].num_elements; e++)
                        af[i].x[e] = wmma::__float_to_tf32(af[i].x[e]);
                }
                #pragma unroll
                for (int j = 0; j < 4; j++) {
                    wmma::load_matrix_sync(bf[j], &Bs[k * 136 + wc * 64 + j * 16], 136);
                    #pragma unroll
                    for (int e = 0; e < bf[j].num_elements; e++)
                        bf[j].x[e] = wmma::__float_to_tf32(bf[j].x[e]);
                }
                #pragma unroll
                for (int i = 0; i < 2; i++)
                    #pragma unroll
                    for (int j = 0; j < 4; j++) {
                        if (g == 0)
                            wmma::mma_sync(acc_z[i][j], af[i], bf[j], acc_z[i][j]);
                        else
                            wmma::mma_sync(acc_h[i][j], af[i], bf[j], acc_h[i][j]);
                    }
            }
        }

        if (g == 0) {
            // znr = 1 - sigmoid(zpre) = 1/(1+exp(zpre)), kept in registers
            #pragma unroll
            for (int i = 0; i < 2; i++)
                #pragma unroll
                for (int j = 0; j < 4; j++)
                    #pragma unroll
                    for (int e = 0; e < acc_z[i][j].num_elements; e++)
                        acc_z[i][j].x[e] = 1.0f / (1.0f + __expf(acc_z[i][j].x[e]));
        }
    }

    // h = relu(znr * tanh(hpre)); element mapping identical across fragments
    #pragma unroll
    for (int i = 0; i < 2; i++)
        #pragma unroll
        for (int j = 0; j < 4; j++) {
            #pragma unroll
            for (int e = 0; e < acc_h[i][j].num_elements; e++) {
                float ht = tanhf(acc_h[i][j].x[e]);
                acc_h[i][j].x[e] = fmaxf(acc_z[i][j].x[e] * ht, 0.0f);
            }
            wmma::store_matrix_sync(
                &g_h[(size_t)(row0 + wr * 32 + i * 16) * 128 + wc * 64 + j * 16],
                acc_h[i][j], 128, wmma::mem_row_major);
        }
}

// ---------------- decoder: out[e] = dot(h[s]*h[d], pw) + pb ----------------
__global__ void decoder_kernel(const void* __restrict__ eli,
                               const float* __restrict__ post_w,
                               const float* __restrict__ post_b,
                               float* __restrict__ out, int EL) {
    int is64 = g_is64;
    int gw = (blockIdx.x * blockDim.x + threadIdx.x) >> 5;
    int lane = threadIdx.x & 31;
    int nw = (gridDim.x * blockDim.x) >> 5;
    float4 w0 = ((const float4*)post_w)[lane * 2];
    float4 w1 = ((const float4*)post_w)[lane * 2 + 1];
    float pw0 = w0.x + w0.y, pw1 = w0.z + w0.w;
    float pw2 = w1.x + w1.y, pw3 = w1.z + w1.w;
    float pb = post_b[0] + post_b[1];
    for (int e = gw; e < EL; e += nw) {
        long long s = ld_idx(eli, e, is64);
        long long d = ld_idx(eli, (long long)EL + e, is64);
        float4 a = ((const float4*)(g_h + (size_t)s * 128))[lane];
        float4 b = ((const float4*)(g_h + (size_t)d * 128))[lane];
        float acc = a.x * b.x * pw0 + a.y * b.y * pw1 + a.z * b.z * pw2 + a.w * b.w * pw3;
        #pragma unroll
        for (int o = 16; o > 0; o >>= 1) acc += __shfl_xor_sync(0xFFFFFFFFu, acc, o);
        if (lane == 0) out[e] = acc + pb;
    }
}

// ---------------- launch ----------------
extern "C" void kernel_launch(void* const* d_in, const int* in_sizes, int n_in,
                              void* d_out, int out_size) {
    const float* x      = (const float*)d_in[0];
    const void*  ei     = d_in[1];
    const void*  eli    = d_in[2];
    const float* pre_w  = (const float*)d_in[3];
    const float* pre_b  = (const float*)d_in[4];
    const float* Wx     = (const float*)d_in[5];
    const float* bx     = (const float*)d_in[6];
    const float* Wh     = (const float*)d_in[7];  (void)Wh;  // H0=0 -> only biases matter
    const float* bh     = (const float*)d_in[8];
    const float* post_w = (const float*)d_in[9];
    const float* post_b = (const float*)d_in[10];
    float* out = (float*)d_out;

    int N    = in_sizes[0] / HD;
    int E    = in_sizes[1] / 2;
    int EL   = in_sizes[2] / 2;
    int npad = ((N + 127) / 128) * 128;

    void *p_degs = nullptr, *p_cnt = nullptr, *p_fill = nullptr;
    cudaGetSymbolAddress(&p_degs, g_degs);
    cudaGetSymbolAddress(&p_cnt,  g_cnt);
    cudaGetSymbolAddress(&p_fill, g_fill);
    cudaMemsetAsync(p_degs, 0, (size_t)N * sizeof(int));
    cudaMemsetAsync(p_cnt,  0, (size_t)N * sizeof(int));
    cudaMemsetAsync(p_fill, 0, (size_t)N * sizeof(int));

    detect_kernel<<<1, 1>>>(ei, N);
    hist_kernel<<<1024, 256>>>(ei, E);
    dinv_kernel<<<(N + 255) / 256, 256>>>(N);
    scan_kernel<<<1, 1024>>>(N);
    fill_kernel<<<1024, 256>>>(ei, E);

    cudaFuncSetAttribute(gemm_pre_tc,
                         cudaFuncAttributeMaxDynamicSharedMemorySize, 150 * 1024);
    gemm_pre_tc<<<npad / 128, 256, 148 * 1024>>>(x, pre_w, pre_b, N);

    spmm_kernel<<<(npad * 32 + 255) / 256, 256>>>(N, npad);

    cudaFuncSetAttribute(gates_tc,
                         cudaFuncAttributeMaxDynamicSharedMemorySize, 214 * 1024);
    gates_tc<<<npad / 128, 256, 2135 * 100>>>(Wx, bx, bh);

    decoder_kernel<<<(EL + 7) / 8, 256>>>(eli, post_w, post_b, out, EL);
}

// round 3
// speedup vs baseline: 1.8968x; 1.0926x over previous
#include <cuda_runtime.h>
#include <cuda_bf16.h>
#include <mma.h>

using namespace nvcuda;

#define NMAX    50000
#define NPADMAX 50176   // ceil(50000/128)*128
#define HD      128
#define EMAX    800000
#define ELMAX   200000

// ---------------- device scratch (no allocations allowed) ----------------
__device__ int   g_degs[NMAX];      // out-degree (node as src) for dinv
__device__ int   g_cnt[NMAX];       // in-count (node as dst) for CSR
__device__ int   g_fill[NMAX];      // CSR fill cursors
__device__ int   g_rowptr[NMAX + 1];
__device__ int   g_col[EMAX];       // CSR: src indices grouped by dst
__device__ int   g_bsum[64];        // scan: per-block sums
__device__ int   g_boff[64];        // scan: per-block exclusive offsets
__device__ float g_dinv[NMAX];
__device__ float g_Xh[(size_t)NPADMAX * HD];
__device__ __nv_bfloat16 g_Xhb[(size_t)NPADMAX * HD];  // bf16 mirror for spmm gather
__device__ float g_LX[(size_t)NPADMAX * HD];
__device__ float g_h [(size_t)NPADMAX * HD];
__device__ int   g_is64;

// ---------------- index-width detection ----------------
// edge_index is int64 in the reference, but JAX without x64 silently yields
// int32. Interpret the first 64 entries as int64: random int32 pairs combine
// to values >= N with overwhelming probability, so 64 in-range int64 reads
// uniquely identify true int64 data.
__global__ void detect_kernel(const void* __restrict__ ei, int n_nodes) {
    const long long* p = (const long long*)ei;
    int ok64 = 1;
    for (int i = 0; i < 64; i++) {
        long long v = p[i];
        if (v < 0 || v >= (long long)n_nodes) { ok64 = 0; break; }
    }
    g_is64 = ok64;
}

__device__ __forceinline__ long long ld_idx(const void* p, long long i, int is64) {
    if (is64) return ((const long long*)p)[i];
    return (long long)((const int*)p)[i];
}

// ---------------- histogram: out-degree (src) + in-count (dst) ----------------
__global__ void hist_kernel(const void* __restrict__ ei, int E) {
    int is64 = g_is64;
    for (int e = blockIdx.x * blockDim.x + threadIdx.x; e < E; e += gridDim.x * blockDim.x) {
        long long s = ld_idx(ei, e, is64);
        long long d = ld_idx(ei, (long long)E + e, is64);
        atomicAdd(&g_degs[s], 1);
        atomicAdd(&g_cnt[d], 1);
    }
}

// ---------------- multi-block exclusive scan of g_cnt -> g_rowptr ----------------
// phase 1: per-block (1024) inclusive scans + block sums
__global__ void scan_local(int n) {
    __shared__ int ws[32];
    int t = threadIdx.x, lane = t & 31, w = t >> 5;
    int i = blockIdx.x * 1024 + t;
    int x = (i < n) ? g_cnt[i] : 0;
    int s = x;
    #pragma unroll
    for (int off = 1; off < 32; off <<= 1) {
        int u = __shfl_up_sync(0xFFFFFFFFu, s, off);
        if (lane >= off) s += u;
    }
    if (lane == 31) ws[w] = s;
    __syncthreads();
    if (w == 0) {
        int v = ws[lane];
        #pragma unroll
        for (int off = 1; off < 32; off <<= 1) {
            int u = __shfl_up_sync(0xFFFFFFFFu, v, off);
            if (lane >= off) v += u;
        }
        ws[lane] = v;
    }
    __syncthreads();
    if (w > 0) s += ws[w - 1];
    if (i < n) g_rowptr[i + 1] = s;
    if (t == 1023) g_bsum[blockIdx.x] = s;
}

// phase 2: tiny serial scan of block sums (nb <= 64)
__global__ void scan_off(int nb) {
    int run = 0;
    for (int b = 0; b < nb; b++) { g_boff[b] = run; run += g_bsum[b]; }
}

// phase 3: apply block offsets; fuse dinv computation
__global__ void scan_apply_dinv(int n) {
    int i = blockIdx.x * 1024 + threadIdx.x;
    if (i < n) {
        g_rowptr[i + 1] += g_boff[blockIdx.x];
        if (i == 0) g_rowptr[0] = 0;
        int d = g_degs[i];
        g_dinv[i] = (d > 0) ? rsqrtf((float)d) : 0.0f;
    }
}

// ---------------- CSR fill: group src indices by dst ----------------
__global__ void fill_kernel(const void* __restrict__ ei, int E) {
    int is64 = g_is64;
    for (int e = blockIdx.x * blockDim.x + threadIdx.x; e < E; e += gridDim.x * blockDim.x) {
        long long s = ld_idx(ei, e, is64);
        long long d = ld_idx(ei, (long long)E + e, is64);
        int pos = g_rowptr[d] + atomicAdd(&g_fill[d], 1);
        g_col[pos] = (int)s;
    }
}

// ---------------- Xh fp32 -> bf16 mirror ----------------
__global__ void xh2bf_kernel(int total4) {
    int i = blockIdx.x * blockDim.x + threadIdx.x;
    if (i < total4) {
        float4 v = ((const float4*)g_Xh)[i];
        __nv_bfloat162 a = __floats2bfloat162_rn(v.x, v.y);
        __nv_bfloat162 b = __floats2bfloat162_rn(v.z, v.w);
        uint2 o;
        o.x = *(unsigned*)&a;
        o.y = *(unsigned*)&b;
        ((uint2*)g_Xhb)[i] = o;
    }
}

// ---------------- SpMM: LX[d] = sum_{e: dst=d} -(dinv[s]*dinv[d]) * Xh[s] ------
// one warp per dst row, bf16 gathers (half traffic), fp32 accumulate, no atomics
__global__ void spmm_kernel(int n, int npad) {
    int gw = (blockIdx.x * blockDim.x + threadIdx.x) >> 5;
    int lane = threadIdx.x & 31;
    if (gw >= npad) return;
    float4 acc = make_float4(0.f, 0.f, 0.f, 0.f);
    if (gw < n) {
        int beg = g_rowptr[gw], end = g_rowptr[gw + 1];
        float dv = -g_dinv[gw];
        const uint2* Xb = (const uint2*)g_Xhb;
        for (int j = beg; j < end; j++) {
            int s = g_col[j];
            float w = dv * g_dinv[s];
            uint2 val = Xb[(size_t)s * 32 + lane];
            __nv_bfloat162 b0 = *(__nv_bfloat162*)&val.x;
            __nv_bfloat162 b1 = *(__nv_bfloat162*)&val.y;
            float2 f0 = __bfloat1622float2(b0);
            float2 f1 = __bfloat1622float2(b1);
            acc.x += w * f0.x; acc.y += w * f0.y;
            acc.z += w * f1.x; acc.w += w * f1.y;
        }
    }
    ((float4*)g_LX)[(size_t)gw * 32 + lane] = acc;
}

// ---------------- tf32 tensor-core GEMM: Xh = x @ pre_w + pre_b ----------------
// block = 128 rows x 128 cols, 8 warps; A, B, bias tiles in smem
__global__ void __launch_bounds__(256)
gemm_pre_tc(const float* __restrict__ x, const float* __restrict__ W,
            const float* __restrict__ bias, int n) {
    extern __shared__ float sm[];
    float* As   = sm;                  // 128 x 136
    float* Bs   = sm + 17408;          // 128 x 136
    float* Bias = sm + 34816;          // 16 x 136
    int t = threadIdx.x;
    int row0 = blockIdx.x * 128;

    const float4* x4 = (const float4*)x;
    #pragma unroll
    for (int i = 0; i < 16; i++) {
        int idx = t + i * 256;
        int r = idx >> 5, c = idx & 31;
        float4 v = make_float4(0.f, 0.f, 0.f, 0.f);
        if (row0 + r < n) v = x4[(size_t)(row0 + r) * 32 + c];
        *(float4*)&As[r * 136 + c * 4] = v;
    }
    const float4* W4 = (const float4*)W;
    #pragma unroll
    for (int i = 0; i < 16; i++) {
        int idx = t + i * 256;
        int r = idx >> 5, c = idx & 31;
        *(float4*)&Bs[r * 136 + c * 4] = W4[idx];
    }
    #pragma unroll
    for (int i = 0; i < 8; i++) {
        int idx = t + i * 256;      // 0..2047
        int r = idx >> 7, c = idx & 127;
        Bias[r * 136 + c] = bias[c];
    }
    __syncthreads();

    int warp = t >> 5;
    int wr = warp & 3;   // 32-row group
    int wc = warp >> 2;  // 64-col group

    wmma::fragment<wmma::accumulator, 16, 16, 8, float> acc[2][4];
    #pragma unroll
    for (int i = 0; i < 2; i++)
        #pragma unroll
        for (int j = 0; j < 4; j++)
            wmma::load_matrix_sync(acc[i][j], &Bias[wc * 64 + j * 16], 136,
                                   wmma::mem_row_major);

    for (int k = 0; k < 128; k += 8) {
        wmma::fragment<wmma::matrix_a, 16, 16, 8, wmma::precision::tf32, wmma::row_major> af[2];
        wmma::fragment<wmma::matrix_b, 16, 16, 8, wmma::precision::tf32, wmma::row_major> bf[4];
        #pragma unroll
        for (int i = 0; i < 2; i++) {
            wmma::load_matrix_sync(af[i], &As[(wr * 32 + i * 16) * 136 + k], 136);
            #pragma unroll
            for (int e = 0; e < af[i].num_elements; e++)
                af[i].x[e] = wmma::__float_to_tf32(af[i].x[e]);
        }
        #pragma unroll
        for (int j = 0; j < 4; j++) {
            wmma::load_matrix_sync(bf[j], &Bs[k * 136 + wc * 64 + j * 16], 136);
            #pragma unroll
            for (int e = 0; e < bf[j].num_elements; e++)
                bf[j].x[e] = wmma::__float_to_tf32(bf[j].x[e]);
        }
        #pragma unroll
        for (int i = 0; i < 2; i++)
            #pragma unroll
            for (int j = 0; j < 4; j++)
                wmma::mma_sync(acc[i][j], af[i], bf[j], acc[i][j]);
    }

    #pragma unroll
    for (int i = 0; i < 2; i++)
        #pragma unroll
        for (int j = 0; j < 4; j++)
            wmma::store_matrix_sync(
                &g_Xh[(size_t)(row0 + wr * 32 + i * 16) * 128 + wc * 64 + j * 16],
                acc[i][j], 128, wmma::mem_row_major);
}

// ---------------- fused gates (tf32 tensor cores) ----------------
// h = relu( sigmoid(-(Xh@Wx00 + LX@Wx01 + bx0 + bh0))
//           * tanh (Xh@Wx20 + LX@Wx21 + bx2 + bh2) )
// A = [Xh | LX] (K=256) stays resident in smem; B streamed per gate in two
// 128-row chunks; gate-z result (1-Z) kept in accumulator registers.
#define GATES_SMEM_FLOATS (33792 + 17408 + 16 * 136)
__global__ void __launch_bounds__(256)
gates_tc(const float* __restrict__ Wx, const float* __restrict__ bx,
         const float* __restrict__ bh) {
    extern __shared__ float sm[];
    float* As   = sm;                   // 128 x 264 = 33792
    float* Bs   = sm + 33792;           // 128 x 136 = 17408
    float* Bias = sm + 33792 + 17408;   // 16 x 136
    int t = threadIdx.x;
    int row0 = blockIdx.x * 128;

    // load A tile: 128 rows x 256 cols (Xh | LX); grid covers padded rows only
    #pragma unroll
    for (int i = 0; i < 32; i++) {
        int idx = t + i * 256;          // 0..8191 float4 slots
        int r = idx >> 6, c = idx & 63; // c in float4 units over 256 floats
        const float4* src4 = (c < 32) ? (const float4*)g_Xh : (const float4*)g_LX;
        float4 v = src4[(size_t)(row0 + r) * 32 + (c & 31)];
        *(float4*)&As[r * 264 + c * 4] = v;
    }

    int warp = t >> 5;
    int wr = warp & 3;
    int wc = warp >> 2;

    wmma::fragment<wmma::accumulator, 16, 16, 8, float> acc_z[2][4];
    wmma::fragment<wmma::accumulator, 16, 16, 8, float> acc_h[2][4];

    #pragma unroll
    for (int g = 0; g < 2; g++) {
        int g3 = (g == 0) ? 0 : 2;          // gate index in Wx/bx/bh
        int wbase = g3 * 2;                 // 16384-float block offset in Wx

        __syncthreads();   // protect Bias/Bs from previous use
        // bias tile: bx[g3] + bh[g3], replicated over 16 rows
        #pragma unroll
        for (int i = 0; i < 8; i++) {
            int idx = t + i * 256;
            int r = idx >> 7, c = idx & 127;
            Bias[r * 136 + c] = bx[g3 * 128 + c] + bh[g3 * 128 + c];
        }
        // B chunk 0: k rows [0,128) = Wx[g3][0]
        const float4* B4 = (const float4*)(Wx + (size_t)wbase * 16384);
        #pragma unroll
        for (int i = 0; i < 16; i++) {
            int idx = t + i * 256;
            int r = idx >> 5, c = idx & 31;
            *(float4*)&Bs[r * 136 + c * 4] = B4[idx];
        }
        __syncthreads();

        #pragma unroll
        for (int i = 0; i < 2; i++)
            #pragma unroll
            for (int j = 0; j < 4; j++) {
                if (g == 0)
                    wmma::load_matrix_sync(acc_z[i][j], &Bias[wc * 64 + j * 16], 136,
                                           wmma::mem_row_major);
                else
                    wmma::load_matrix_sync(acc_h[i][j], &Bias[wc * 64 + j * 16], 136,
                                           wmma::mem_row_major);
            }

        #pragma unroll
        for (int c2 = 0; c2 < 2; c2++) {
            if (c2 == 1) {
                __syncthreads();
                const float4* B4b = (const float4*)(Wx + (size_t)(wbase + 1) * 16384);
                #pragma unroll
                for (int i = 0; i < 16; i++) {
                    int idx = t + i * 256;
                    int r = idx >> 5, c = idx & 31;
                    *(float4*)&Bs[r * 136 + c * 4] = B4b[idx];
                }
                __syncthreads();
            }
            for (int k = 0; k < 128; k += 8) {
                wmma::fragment<wmma::matrix_a, 16, 16, 8, wmma::precision::tf32, wmma::row_major> af[2];
                wmma::fragment<wmma::matrix_b, 16, 16, 8, wmma::precision::tf32, wmma::row_major> bf[4];
                #pragma unroll
                for (int i = 0; i < 2; i++) {
                    wmma::load_matrix_sync(af[i], &As[(wr * 32 + i * 16) * 264 + c2 * 128 + k], 264);
                    #pragma unroll
                    for (int e = 0; e < af[i].num_elements; e++)
                        af[i].x[e] = wmma::__float_to_tf32(af[i].x[e]);
                }
                #pragma unroll
                for (int j = 0; j < 4; j++) {
                    wmma::load_matrix_sync(bf[j], &Bs[k * 136 + wc * 64 + j * 16], 136);
                    #pragma unroll
                    for (int e = 0; e < bf[j].num_elements; e++)
                        bf[j].x[e] = wmma::__float_to_tf32(bf[j].x[e]);
                }
                #pragma unroll
                for (int i = 0; i < 2; i++)
                    #pragma unroll
                    for (int j = 0; j < 4; j++) {
                        if (g == 0)
                            wmma::mma_sync(acc_z[i][j], af[i], bf[j], acc_z[i][j]);
                        else
                            wmma::mma_sync(acc_h[i][j], af[i], bf[j], acc_h[i][j]);
                    }
            }
        }

        if (g == 0) {
            // znr = 1 - sigmoid(zpre) = 1/(1+exp(zpre)), kept in registers
            #pragma unroll
            for (int i = 0; i < 2; i++)
                #pragma unroll
                for (int j = 0; j < 4; j++)
                    #pragma unroll
                    for (int e = 0; e < acc_z[i][j].num_elements; e++)
                        acc_z[i][j].x[e] = 1.0f / (1.0f + __expf(acc_z[i][j].x[e]));
        }
    }

    // h = relu(znr * tanh(hpre)); element mapping identical across fragments
    #pragma unroll
    for (int i = 0; i < 2; i++)
        #pragma unroll
        for (int j = 0; j < 4; j++) {
            #pragma unroll
            for (int e = 0; e < acc_h[i][j].num_elements; e++) {
                float ht = tanhf(acc_h[i][j].x[e]);
                acc_h[i][j].x[e] = fmaxf(acc_z[i][j].x[e] * ht, 0.0f);
            }
            wmma::store_matrix_sync(
                &g_h[(size_t)(row0 + wr * 32 + i * 16) * 128 + wc * 64 + j * 16],
                acc_h[i][j], 128, wmma::mem_row_major);
        }
}

// ---------------- decoder: out[e] = dot(h[s]*h[d], pw) + pb ----------------
__global__ void decoder_kernel(const void* __restrict__ eli,
                               const float* __restrict__ post_w,
                               const float* __restrict__ post_b,
                               float* __restrict__ out, int EL) {
    int is64 = g_is64;
    int gw = (blockIdx.x * blockDim.x + threadIdx.x) >> 5;
    int lane = threadIdx.x & 31;
    int nw = (gridDim.x * blockDim.x) >> 5;
    float4 w0 = ((const float4*)post_w)[lane * 2];
    float4 w1 = ((const float4*)post_w)[lane * 2 + 1];
    float pw0 = w0.x + w0.y, pw1 = w0.z + w0.w;
    float pw2 = w1.x + w1.y, pw3 = w1.z + w1.w;
    float pb = post_b[0] + post_b[1];
    for (int e = gw; e < EL; e += nw) {
        long long s = ld_idx(eli, e, is64);
        long long d = ld_idx(eli, (long long)EL + e, is64);
        float4 a = ((const float4*)(g_h + (size_t)s * 128))[lane];
        float4 b = ((const float4*)(g_h + (size_t)d * 128))[lane];
        float acc = a.x * b.x * pw0 + a.y * b.y * pw1 + a.z * b.z * pw2 + a.w * b.w * pw3;
        #pragma unroll
        for (int o = 16; o > 0; o >>= 1) acc += __shfl_xor_sync(0xFFFFFFFFu, acc, o);
        if (lane == 0) out[e] = acc + pb;
    }
}

// ---------------- launch ----------------
extern "C" void kernel_launch(void* const* d_in, const int* in_sizes, int n_in,
                              void* d_out, int out_size) {
    const float* x      = (const float*)d_in[0];
    const void*  ei     = d_in[1];
    const void*  eli    = d_in[2];
    const float* pre_w  = (const float*)d_in[3];
    const float* pre_b  = (const float*)d_in[4];
    const float* Wx     = (const float*)d_in[5];
    const float* bx     = (const float*)d_in[6];
    const float* Wh     = (const float*)d_in[7];  (void)Wh;  // H0=0 -> only biases matter
    const float* bh     = (const float*)d_in[8];
    const float* post_w = (const float*)d_in[9];
    const float* post_b = (const float*)d_in[10];
    float* out = (float*)d_out;

    int N    = in_sizes[0] / HD;
    int E    = in_sizes[1] / 2;
    int EL   = in_sizes[2] / 2;
    int npad = ((N + 127) / 128) * 128;
    int nb   = (N + 1023) / 1024;

    void *p_degs = nullptr, *p_cnt = nullptr, *p_fill = nullptr;
    cudaGetSymbolAddress(&p_degs, g_degs);
    cudaGetSymbolAddress(&p_cnt,  g_cnt);
    cudaGetSymbolAddress(&p_fill, g_fill);
    cudaMemsetAsync(p_degs, 0, (size_t)N * sizeof(int));
    cudaMemsetAsync(p_cnt,  0, (size_t)N * sizeof(int));
    cudaMemsetAsync(p_fill, 0, (size_t)N * sizeof(int));

    detect_kernel<<<1, 1>>>(ei, N);
    hist_kernel<<<1024, 256>>>(ei, E);
    scan_local<<<nb, 1024>>>(N);
    scan_off<<<1, 1>>>(nb);
    scan_apply_dinv<<<nb, 1024>>>(N);
    fill_kernel<<<1024, 256>>>(ei, E);

    cudaFuncSetAttribute(gemm_pre_tc,
                         cudaFuncAttributeMaxDynamicSharedMemorySize, 150 * 1024);
    gemm_pre_tc<<<npad / 128, 256, (17408 + 17408 + 16 * 136) * 4>>>(x, pre_w, pre_b, N);

    xh2bf_kernel<<<(npad * 32 + 255) / 256, 256>>>(npad * 32);

    spmm_kernel<<<(npad * 32 + 255) / 256, 256>>>(N, npad);

    cudaFuncSetAttribute(gates_tc,
                         cudaFuncAttributeMaxDynamicSharedMemorySize, 220 * 1024);
    gates_tc<<<npad / 128, 256, GATES_SMEM_FLOATS * 4>>>(Wx, bx, bh);

    decoder_kernel<<<(EL + 7) / 8, 256>>>(eli, post_w, post_b, out, EL);
}

// round 4
// speedup vs baseline: 2.0136x; 1.0616x over previous
#include <cuda_runtime.h>
#include <cuda_bf16.h>
#include <mma.h>

using namespace nvcuda;

#define NMAX    50000
#define NPADMAX 50176   // ceil(50000/128)*128
#define HD      128
#define EMAX    800000

// ---------------- device scratch (no allocations allowed) ----------------
__device__ int   g_ints[2 * NMAX];   // [0,NMAX): out-deg (src); [NMAX,2N): in-cnt (dst)
__device__ int   g_fill[NMAX];       // CSR fill cursors (init to rowptr in scan_apply)
__device__ int   g_rowptr[NMAX + 1];
__device__ int   g_col[EMAX];        // CSR: src indices grouped by dst
__device__ int   g_bsum[64];         // scan: per-block sums
__device__ float g_dinv[NMAX];
__device__ float g_Xh[(size_t)NPADMAX * HD];
__device__ __nv_bfloat16 g_Xhb[(size_t)NPADMAX * HD];  // bf16 mirror for spmm gather
__device__ float g_LX[(size_t)NPADMAX * HD];
__device__ float g_h [(size_t)NPADMAX * HD];

// ---------------- index-width detection (per-block, from L2) ----------------
// edge buffers are int64 in the reference, but JAX without x64 silently yields
// int32. Interpret the first 64 entries as int64: random int32 pairs combine
// to values >= N with overwhelming probability, so 64 in-range int64 reads
// uniquely identify true int64 data. Every block sniffs independently (reads
// hit L2), so no separate detect kernel / global flag is needed.
__device__ __forceinline__ int detect64(const void* p, int n_nodes) {
    const long long* q = (const long long*)p;
    int ok = 1;
    #pragma unroll 1
    for (int i = 0; i < 64; i++) {
        long long v = q[i];
        if (v < 0 || v >= (long long)n_nodes) { ok = 0; break; }
    }
    return ok;
}

__device__ __forceinline__ long long ld_idx(const void* p, long long i, int is64) {
    if (is64) return ((const long long*)p)[i];
    return (long long)((const int*)p)[i];
}

// ---------------- histogram: out-degree (src) + in-count (dst) ----------------
__global__ void hist_kernel(const void* __restrict__ ei, int E, int n_nodes) {
    __shared__ int sh64;
    if (threadIdx.x == 0) sh64 = detect64(ei, n_nodes);
    __syncthreads();
    int is64 = sh64;
    for (int e = blockIdx.x * blockDim.x + threadIdx.x; e < E; e += gridDim.x * blockDim.x) {
        long long s = ld_idx(ei, e, is64);
        long long d = ld_idx(ei, (long long)E + e, is64);
        atomicAdd(&g_ints[s], 1);
        atomicAdd(&g_ints[NMAX + d], 1);
    }
}

// ---------------- scan phase 1: per-block (1024) inclusive scans + block sums ----
__global__ void scan_local(int n) {
    __shared__ int ws[32];
    int t = threadIdx.x, lane = t & 31, w = t >> 5;
    int i = blockIdx.x * 1024 + t;
    int s = (i < n) ? g_ints[NMAX + i] : 0;
    #pragma unroll
    for (int off = 1; off < 32; off <<= 1) {
        int u = __shfl_up_sync(0xFFFFFFFFu, s, off);
        if (lane >= off) s += u;
    }
    if (lane == 31) ws[w] = s;
    __syncthreads();
    if (w == 0) {
        int v = ws[lane];
        #pragma unroll
        for (int off = 1; off < 32; off <<= 1) {
            int u = __shfl_up_sync(0xFFFFFFFFu, v, off);
            if (lane >= off) v += u;
        }
        ws[lane] = v;
    }
    __syncthreads();
    if (w > 0) s += ws[w - 1];
    if (i < n) g_rowptr[i + 1] = s;
    if (t == 1023) g_bsum[blockIdx.x] = s;
}

// ---------------- scan phase 2: apply offsets (computed inline) + dinv + cursors ---
__global__ void scan_apply_dinv(int n) {
    __shared__ int boff_sm;
    int bid = blockIdx.x;
    if (threadIdx.x < 32) {
        int v = 0;
        for (int j = threadIdx.x; j < bid; j += 32) v += g_bsum[j];
        #pragma unroll
        for (int off = 16; off > 0; off >>= 1) v += __shfl_xor_sync(0xFFFFFFFFu, v, off);
        if (threadIdx.x == 0) boff_sm = v;
    }
    __syncthreads();
    int boff = boff_sm;
    int i = bid * 1024 + threadIdx.x;
    if (i < n) {
        int rp = g_rowptr[i + 1] + boff;
        g_rowptr[i + 1] = rp;
        if (i == 0) g_rowptr[0] = 0;
        g_fill[i] = rp - g_ints[NMAX + i];   // row start = rowptr[i]
        int d = g_ints[i];
        g_dinv[i] = (d > 0) ? rsqrtf((float)d) : 0.0f;
    }
}

// ---------------- CSR fill: group src indices by dst (cursors pre-initialized) ----
__global__ void fill_kernel(const void* __restrict__ ei, int E, int n_nodes) {
    __shared__ int sh64;
    if (threadIdx.x == 0) sh64 = detect64(ei, n_nodes);
    __syncthreads();
    int is64 = sh64;
    for (int e = blockIdx.x * blockDim.x + threadIdx.x; e < E; e += gridDim.x * blockDim.x) {
        long long s = ld_idx(ei, e, is64);
        long long d = ld_idx(ei, (long long)E + e, is64);
        int pos = atomicAdd(&g_fill[d], 1);
        g_col[pos] = (int)s;
    }
}

// ---------------- SpMM: LX[d] = sum_{e: dst=d} -(dinv[s]*dinv[d]) * Xh[s] ------
// one warp per dst row, bf16 gathers (half traffic), fp32 accumulate, no atomics
__global__ void spmm_kernel(int n, int npad) {
    int gw = (blockIdx.x * blockDim.x + threadIdx.x) >> 5;
    int lane = threadIdx.x & 31;
    if (gw >= npad) return;
    float4 acc = make_float4(0.f, 0.f, 0.f, 0.f);
    if (gw < n) {
        int beg = g_rowptr[gw], end = g_rowptr[gw + 1];
        float dv = -g_dinv[gw];
        const uint2* Xb = (const uint2*)g_Xhb;
        for (int j = beg; j < end; j++) {
            int s = g_col[j];
            float w = dv * g_dinv[s];
            uint2 val = Xb[(size_t)s * 32 + lane];
            __nv_bfloat162 b0 = *(__nv_bfloat162*)&val.x;
            __nv_bfloat162 b1 = *(__nv_bfloat162*)&val.y;
            float2 f0 = __bfloat1622float2(b0);
            float2 f1 = __bfloat1622float2(b1);
            acc.x += w * f0.x; acc.y += w * f0.y;
            acc.z += w * f1.x; acc.w += w * f1.y;
        }
    }
    ((float4*)g_LX)[(size_t)gw * 32 + lane] = acc;
}

// ---------------- tf32 tensor-core GEMM: Xh = x @ pre_w + pre_b ----------------
// block = 128 rows x 128 cols, 8 warps; epilogue writes fp32 AND bf16 mirror
#define PRE_SMEM_FLOATS (17408 + 17408 + 16 * 136)
__global__ void __launch_bounds__(256)
gemm_pre_tc(const float* __restrict__ x, const float* __restrict__ W,
            const float* __restrict__ bias, int n) {
    extern __shared__ float sm[];
    float* As   = sm;                  // 128 x 136
    float* Bs   = sm + 17408;          // 128 x 136
    float* Bias = sm + 34816;          // 16 x 136
    int t = threadIdx.x;
    int row0 = blockIdx.x * 128;

    const float4* x4 = (const float4*)x;
    #pragma unroll
    for (int i = 0; i < 16; i++) {
        int idx = t + i * 256;
        int r = idx >> 5, c = idx & 31;
        float4 v = make_float4(0.f, 0.f, 0.f, 0.f);
        if (row0 + r < n) v = x4[(size_t)(row0 + r) * 32 + c];
        *(float4*)&As[r * 136 + c * 4] = v;
    }
    const float4* W4 = (const float4*)W;
    #pragma unroll
    for (int i = 0; i < 16; i++) {
        int idx = t + i * 256;
        int r = idx >> 5, c = idx & 31;
        *(float4*)&Bs[r * 136 + c * 4] = W4[idx];
    }
    #pragma unroll
    for (int i = 0; i < 8; i++) {
        int idx = t + i * 256;      // 0..2047
        int r = idx >> 7, c = idx & 127;
        Bias[r * 136 + c] = bias[c];
    }
    __syncthreads();

    int warp = t >> 5;
    int wr = warp & 3;   // 32-row group
    int wc = warp >> 2;  // 64-col group

    wmma::fragment<wmma::accumulator, 16, 16, 8, float> acc[2][4];
    #pragma unroll
    for (int i = 0; i < 2; i++)
        #pragma unroll
        for (int j = 0; j < 4; j++)
            wmma::load_matrix_sync(acc[i][j], &Bias[wc * 64 + j * 16], 136,
                                   wmma::mem_row_major);

    for (int k = 0; k < 128; k += 8) {
        wmma::fragment<wmma::matrix_a, 16, 16, 8, wmma::precision::tf32, wmma::row_major> af[2];
        wmma::fragment<wmma::matrix_b, 16, 16, 8, wmma::precision::tf32, wmma::row_major> bf[4];
        #pragma unroll
        for (int i = 0; i < 2; i++) {
            wmma::load_matrix_sync(af[i], &As[(wr * 32 + i * 16) * 136 + k], 136);
            #pragma unroll
            for (int e = 0; e < af[i].num_elements; e++)
                af[i].x[e] = wmma::__float_to_tf32(af[i].x[e]);
        }
        #pragma unroll
        for (int j = 0; j < 4; j++) {
            wmma::load_matrix_sync(bf[j], &Bs[k * 136 + wc * 64 + j * 16], 136);
            #pragma unroll
            for (int e = 0; e < bf[j].num_elements; e++)
                bf[j].x[e] = wmma::__float_to_tf32(bf[j].x[e]);
        }
        #pragma unroll
        for (int i = 0; i < 2; i++)
            #pragma unroll
            for (int j = 0; j < 4; j++)
                wmma::mma_sync(acc[i][j], af[i], bf[j], acc[i][j]);
    }

    // epilogue: stage result in As, then write fp32 + bf16 mirror
    __syncthreads();  // all warps done reading As
    #pragma unroll
    for (int i = 0; i < 2; i++)
        #pragma unroll
        for (int j = 0; j < 4; j++)
            wmma::store_matrix_sync(&As[(wr * 32 + i * 16) * 136 + wc * 64 + j * 16],
                                    acc[i][j], 136, wmma::mem_row_major);
    __syncthreads();
    #pragma unroll
    for (int i = 0; i < 16; i++) {
        int idx = t + i * 256;
        int r = idx >> 5, c = idx & 31;
        float4 v = *(const float4*)&As[r * 136 + c * 4];
        size_t off = (size_t)(row0 + r) * 32 + c;
        ((float4*)g_Xh)[off] = v;
        __nv_bfloat162 a = __floats2bfloat162_rn(v.x, v.y);
        __nv_bfloat162 b = __floats2bfloat162_rn(v.z, v.w);
        uint2 o;
        o.x = *(unsigned*)&a;
        o.y = *(unsigned*)&b;
        ((uint2*)g_Xhb)[off] = o;
    }
}

// ---------------- fused gates (tf32 tensor cores) ----------------
// h = relu( sigmoid(-(Xh@Wx00 + LX@Wx01 + bx0 + bh0))
//           * tanh (Xh@Wx20 + LX@Wx21 + bx2 + bh2) )
// A = [Xh | LX] (K=256) stays resident in smem; B streamed per gate in two
// 128-row chunks; gate-z result (1-Z) kept in accumulator registers.
#define GATES_SMEM_FLOATS (33792 + 17408 + 16 * 136)
__global__ void __launch_bounds__(256)
gates_tc(const float* __restrict__ Wx, const float* __restrict__ bx,
         const float* __restrict__ bh) {
    extern __shared__ float sm[];
    float* As   = sm;                   // 128 x 264 = 33792
    float* Bs   = sm + 33792;           // 128 x 136 = 17408
    float* Bias = sm + 33792 + 17408;   // 16 x 136
    int t = threadIdx.x;
    int row0 = blockIdx.x * 128;

    // load A tile: 128 rows x 256 cols (Xh | LX); grid covers padded rows only
    #pragma unroll
    for (int i = 0; i < 32; i++) {
        int idx = t + i * 256;          // 0..8191 float4 slots
        int r = idx >> 6, c = idx & 63; // c in float4 units over 256 floats
        const float4* src4 = (c < 32) ? (const float4*)g_Xh : (const float4*)g_LX;
        float4 v = src4[(size_t)(row0 + r) * 32 + (c & 31)];
        *(float4*)&As[r * 264 + c * 4] = v;
    }

    int warp = t >> 5;
    int wr = warp & 3;
    int wc = warp >> 2;

    wmma::fragment<wmma::accumulator, 16, 16, 8, float> acc_z[2][4];
    wmma::fragment<wmma::accumulator, 16, 16, 8, float> acc_h[2][4];

    #pragma unroll
    for (int g = 0; g < 2; g++) {
        int g3 = (g == 0) ? 0 : 2;          // gate index in Wx/bx/bh
        int wbase = g3 * 2;                 // 16384-float block offset in Wx

        __syncthreads();   // protect Bias/Bs from previous use
        // bias tile: bx[g3] + bh[g3], replicated over 16 rows
        #pragma unroll
        for (int i = 0; i < 8; i++) {
            int idx = t + i * 256;
            int r = idx >> 7, c = idx & 127;
            Bias[r * 136 + c] = bx[g3 * 128 + c] + bh[g3 * 128 + c];
        }
        // B chunk 0: k rows [0,128) = Wx[g3][0]
        const float4* B4 = (const float4*)(Wx + (size_t)wbase * 16384);
        #pragma unroll
        for (int i = 0; i < 16; i++) {
            int idx = t + i * 256;
            int r = idx >> 5, c = idx & 31;
            *(float4*)&Bs[r * 136 + c * 4] = B4[idx];
        }
        __syncthreads();

        #pragma unroll
        for (int i = 0; i < 2; i++)
            #pragma unroll
            for (int j = 0; j < 4; j++) {
                if (g == 0)
                    wmma::load_matrix_sync(acc_z[i][j], &Bias[wc * 64 + j * 16], 136,
                                           wmma::mem_row_major);
                else
                    wmma::load_matrix_sync(acc_h[i][j], &Bias[wc * 64 + j * 16], 136,
                                           wmma::mem_row_major);
            }

        #pragma unroll
        for (int c2 = 0; c2 < 2; c2++) {
            if (c2 == 1) {
                __syncthreads();
                const float4* B4b = (const float4*)(Wx + (size_t)(wbase + 1) * 16384);
                #pragma unroll
                for (int i = 0; i < 16; i++) {
                    int idx = t + i * 256;
                    int r = idx >> 5, c = idx & 31;
                    *(float4*)&Bs[r * 136 + c * 4] = B4b[idx];
                }
                __syncthreads();
            }
            for (int k = 0; k < 128; k += 8) {
                wmma::fragment<wmma::matrix_a, 16, 16, 8, wmma::precision::tf32, wmma::row_major> af[2];
                wmma::fragment<wmma::matrix_b, 16, 16, 8, wmma::precision::tf32, wmma::row_major> bf[4];
                #pragma unroll
                for (int i = 0; i < 2; i++) {
                    wmma::load_matrix_sync(af[i], &As[(wr * 32 + i * 16) * 264 + c2 * 128 + k], 264);
                    #pragma unroll
                    for (int e = 0; e < af[i].num_elements; e++)
                        af[i].x[e] = wmma::__float_to_tf32(af[i].x[e]);
                }
                #pragma unroll
                for (int j = 0; j < 4; j++) {
                    wmma::load_matrix_sync(bf[j], &Bs[k * 136 + wc * 64 + j * 16], 136);
                    #pragma unroll
                    for (int e = 0; e < bf[j].num_elements; e++)
                        bf[j].x[e] = wmma::__float_to_tf32(bf[j].x[e]);
                }
                #pragma unroll
                for (int i = 0; i < 2; i++)
                    #pragma unroll
                    for (int j = 0; j < 4; j++) {
                        if (g == 0)
                            wmma::mma_sync(acc_z[i][j], af[i], bf[j], acc_z[i][j]);
                        else
                            wmma::mma_sync(acc_h[i][j], af[i], bf[j], acc_h[i][j]);
                    }
            }
        }

        if (g == 0) {
            // znr = 1 - sigmoid(zpre) = 1/(1+exp(zpre)), kept in registers
            #pragma unroll
            for (int i = 0; i < 2; i++)
                #pragma unroll
                for (int j = 0; j < 4; j++)
                    #pragma unroll
                    for (int e = 0; e < acc_z[i][j].num_elements; e++)
                        acc_z[i][j].x[e] = 1.0f / (1.0f + __expf(acc_z[i][j].x[e]));
        }
    }

    // h = relu(znr * tanh(hpre)); element mapping identical across fragments
    #pragma unroll
    for (int i = 0; i < 2; i++)
        #pragma unroll
        for (int j = 0; j < 4; j++) {
            #pragma unroll
            for (int e = 0; e < acc_h[i][j].num_elements; e++) {
                float ht = tanhf(acc_h[i][j].x[e]);
                acc_h[i][j].x[e] = fmaxf(acc_z[i][j].x[e] * ht, 0.0f);
            }
            wmma::store_matrix_sync(
                &g_h[(size_t)(row0 + wr * 32 + i * 16) * 128 + wc * 64 + j * 16],
                acc_h[i][j], 128, wmma::mem_row_major);
        }
}

// ---------------- decoder: out[e] = dot(h[s]*h[d], pw) + pb ----------------
__global__ void decoder_kernel(const void* __restrict__ eli,
                               const float* __restrict__ post_w,
                               const float* __restrict__ post_b,
                               float* __restrict__ out, int EL, int n_nodes) {
    __shared__ int sh64;
    if (threadIdx.x == 0) sh64 = detect64(eli, n_nodes);
    __syncthreads();
    int is64 = sh64;
    int gw = (blockIdx.x * blockDim.x + threadIdx.x) >> 5;
    int lane = threadIdx.x & 31;
    int nw = (gridDim.x * blockDim.x) >> 5;
    float4 w0 = ((const float4*)post_w)[lane * 2];
    float4 w1 = ((const float4*)post_w)[lane * 2 + 1];
    float pw0 = w0.x + w0.y, pw1 = w0.z + w0.w;
    float pw2 = w1.x + w1.y, pw3 = w1.z + w1.w;
    float pb = post_b[0] + post_b[1];
    for (int e = gw; e < EL; e += nw) {
        long long s = ld_idx(eli, e, is64);
        long long d = ld_idx(eli, (long long)EL + e, is64);
        float4 a = ((const float4*)(g_h + (size_t)s * 128))[lane];
        float4 b = ((const float4*)(g_h + (size_t)d * 128))[lane];
        float acc = a.x * b.x * pw0 + a.y * b.y * pw1 + a.z * b.z * pw2 + a.w * b.w * pw3;
        #pragma unroll
        for (int o = 16; o > 0; o >>= 1) acc += __shfl_xor_sync(0xFFFFFFFFu, acc, o);
        if (lane == 0) out[e] = acc + pb;
    }
}

// ---------------- launch ----------------
extern "C" void kernel_launch(void* const* d_in, const int* in_sizes, int n_in,
                              void* d_out, int out_size) {
    const float* x      = (const float*)d_in[0];
    const void*  ei     = d_in[1];
    const void*  eli    = d_in[2];
    const float* pre_w  = (const float*)d_in[3];
    const float* pre_b  = (const float*)d_in[4];
    const float* Wx     = (const float*)d_in[5];
    const float* bx     = (const float*)d_in[6];
    const float* Wh     = (const float*)d_in[7];  (void)Wh;  // H0=0 -> only biases matter
    const float* bh     = (const float*)d_in[8];
    const float* post_w = (const float*)d_in[9];
    const float* post_b = (const float*)d_in[10];
    float* out = (float*)d_out;

    int N    = in_sizes[0] / HD;
    int E    = in_sizes[1] / 2;
    int EL   = in_sizes[2] / 2;
    int npad = ((N + 127) / 128) * 128;
    int nb   = (N + 1023) / 1024;

    // fork: gemm_pre (feature path) runs concurrently with the edge path
    cudaStream_t s2;
    cudaStreamCreateWithFlags(&s2, cudaStreamNonBlocking);
    cudaEvent_t evA, evB;
    cudaEventCreateWithFlags(&evA, cudaEventDisableTiming);
    cudaEventCreateWithFlags(&evB, cudaEventDisableTiming);

    cudaEventRecord(evA, 0);
    cudaStreamWaitEvent(s2, evA, 0);
    cudaFuncSetAttribute(gemm_pre_tc,
                         cudaFuncAttributeMaxDynamicSharedMemorySize, 150 * 1024);
    gemm_pre_tc<<<npad / 128, 256, PRE_SMEM_FLOATS * 4, s2>>>(x, pre_w, pre_b, N);
    cudaEventRecord(evB, s2);

    // edge path on the capture stream
    void* p_ints = nullptr;
    cudaGetSymbolAddress(&p_ints, g_ints);
    cudaMemsetAsync(p_ints, 0, (size_t)2 * NMAX * sizeof(int));

    hist_kernel<<<1024, 256>>>(ei, E, N);
    scan_local<<<nb, 1024>>>(N);
    scan_apply_dinv<<<nb, 1024>>>(N);
    fill_kernel<<<1024, 256>>>(ei, E, N);

    // join: spmm needs both CSR (edge path) and Xh bf16 (feature path)
    cudaStreamWaitEvent(0, evB, 0);

    spmm_kernel<<<(npad * 32 + 255) / 256, 256>>>(N, npad);

    cudaFuncSetAttribute(gates_tc,
                         cudaFuncAttributeMaxDynamicSharedMemorySize, 220 * 1024);
    gates_tc<<<npad / 128, 256, GATES_SMEM_FLOATS * 4>>>(Wx, bx, bh);

    decoder_kernel<<<(EL + 7) / 8, 256>>>(eli, post_w, post_b, out, EL, N);
}

// round 5
// speedup vs baseline: 2.5769x; 1.2798x over previous
#include <cuda_runtime.h>
#include <cuda_fp16.h>
#include <mma.h>

using namespace nvcuda;

#define NMAX    50000
#define NPADMAX 50176   // ceil(50000/128)*128
#define HD      128
#define EMAX    800000

// ---------------- device scratch (no allocations allowed) ----------------
__device__ int    g_ints[2 * NMAX + 64]; // [0,N): out-deg; [NMAX,NMAX+N): in-cnt; [2N..): scan flags
__device__ int    g_pref[64];            // scan block aggregates (gated by flags)
__device__ int    g_fill[NMAX];          // CSR fill cursors
__device__ int    g_rowptr[NMAX + 1];
__device__ int    g_col[EMAX];           // CSR: src indices grouped by dst
__device__ float  g_dinv[NMAX];
__device__ __half g_Xhh[(size_t)NPADMAX * HD]; // fp16 Xh (only consumer format)
__device__ __half g_hh [(size_t)NPADMAX * HD]; // fp16 h for decoder

// ---------------- helpers ----------------
__device__ __forceinline__ void st4h(__half* p, float4 v) {
    __half2 a = __floats2half2_rn(v.x, v.y);
    __half2 b = __floats2half2_rn(v.z, v.w);
    uint2 o;
    o.x = *(unsigned*)&a;
    o.y = *(unsigned*)&b;
    *(uint2*)p = o;
}

// edge buffers are declared int64 in the reference, but JAX without x64
// silently yields int32. Interpret the first 64 entries as int64: random
// int32 pairs combine to values >= N with overwhelming probability, so 64
// in-range int64 reads uniquely identify true int64 data. Every block sniffs
// independently (reads hit L2).
__device__ __forceinline__ int detect64(const void* p, int n_nodes) {
    const long long* q = (const long long*)p;
    int ok = 1;
    #pragma unroll 1
    for (int i = 0; i < 64; i++) {
        long long v = q[i];
        if (v < 0 || v >= (long long)n_nodes) { ok = 0; break; }
    }
    return ok;
}

__device__ __forceinline__ long long ld_idx(const void* p, long long i, int is64) {
    if (is64) return ((const long long*)p)[i];
    return (long long)((const int*)p)[i];
}

// ---------------- histogram: out-degree (src) + in-count (dst) ----------------
__global__ void hist_kernel(const void* __restrict__ ei, int E, int n_nodes) {
    __shared__ int sh64;
    if (threadIdx.x == 0) sh64 = detect64(ei, n_nodes);
    __syncthreads();
    int is64 = sh64;
    for (int e = blockIdx.x * blockDim.x + threadIdx.x; e < E; e += gridDim.x * blockDim.x) {
        long long s = ld_idx(ei, e, is64);
        long long d = ld_idx(ei, (long long)E + e, is64);
        atomicAdd(&g_ints[s], 1);
        atomicAdd(&g_ints[NMAX + d], 1);
    }
}

// ---------------- fused scan (decoupled lookback) + dinv + fill cursors ----------
// one kernel: per-block scan, publish aggregate, parallel lookback over all
// predecessor aggregates (all blocks resident: nb <= 49 << 148 SMs).
__global__ void scan_fused(int n) {
    __shared__ int ws[32];
    __shared__ int boff_sm;
    int t = threadIdx.x, lane = t & 31, w = t >> 5;
    int bid = blockIdx.x;
    int i = bid * 1024 + t;
    int cnt = (i < n) ? g_ints[NMAX + i] : 0;
    int s = cnt;
    #pragma unroll
    for (int off = 1; off < 32; off <<= 1) {
        int u = __shfl_up_sync(0xFFFFFFFFu, s, off);
        if (lane >= off) s += u;
    }
    if (lane == 31) ws[w] = s;
    __syncthreads();
    if (w == 0) {
        int v = ws[lane];
        #pragma unroll
        for (int off = 1; off < 32; off <<= 1) {
            int u = __shfl_up_sync(0xFFFFFFFFu, v, off);
            if (lane >= off) v += u;
        }
        ws[lane] = v;
    }
    __syncthreads();
    if (w > 0) s += ws[w - 1];
    // publish block aggregate
    if (t == 1023) {
        g_pref[bid] = s;
        __threadfence();
        ((volatile int*)g_ints)[2 * NMAX + bid] = 1;
    }
    // parallel lookback: warp 0 sums all predecessor aggregates
    if (w == 0) {
        int v = 0;
        for (int j = lane; j < bid; j += 32) {
            volatile int* fl = (volatile int*)&g_ints[2 * NMAX + j];
            while (*fl == 0) {}
            v += g_pref[j];
        }
        #pragma unroll
        for (int off = 16; off > 0; off >>= 1) v += __shfl_xor_sync(0xFFFFFFFFu, v, off);
        if (lane == 0) boff_sm = v;
    }
    __syncthreads();
    __threadfence_block();
    int boff = boff_sm;
    if (i < n) {
        int rp = s + boff;           // inclusive prefix -> rowptr[i+1]
        g_rowptr[i + 1] = rp;
        if (i == 0) g_rowptr[0] = 0;
        g_fill[i] = rp - cnt;        // row start cursor
        int d = g_ints[i];
        g_dinv[i] = (d > 0) ? rsqrtf((float)d) : 0.0f;
    }
}

// ---------------- CSR fill: group src indices by dst ----------------
__global__ void fill_kernel(const void* __restrict__ ei, int E, int n_nodes) {
    __shared__ int sh64;
    if (threadIdx.x == 0) sh64 = detect64(ei, n_nodes);
    __syncthreads();
    int is64 = sh64;
    for (int e = blockIdx.x * blockDim.x + threadIdx.x; e < E; e += gridDim.x * blockDim.x) {
        long long s = ld_idx(ei, e, is64);
        long long d = ld_idx(ei, (long long)E + e, is64);
        int pos = atomicAdd(&g_fill[d], 1);
        g_col[pos] = (int)s;
    }
}

// ---------------- fp16 tensor-core GEMM: Xhh = fp16(x @ pre_w + pre_b) -----------
// 128x128 tile, 8 warps, m16n16k16; ~78KB smem -> 2 CTAs/SM
#define PRE_SMEM (34816 + 34816 + 8704)
__global__ void __launch_bounds__(256)
gemm_pre_fp16(const float* __restrict__ x, const float* __restrict__ W,
              const float* __restrict__ bias, int n) {
    extern __shared__ char smc[];
    __half* As  = (__half*)smc;             // 128 x 136 half
    __half* Bs  = (__half*)(smc + 34816);   // 128 x 136 half
    float* Bias = (float*)(smc + 69632);    // 16 x 136 float
    float* Stg  = (float*)smc;              // epilogue stage: 128 x 136 float (reuse)
    int t = threadIdx.x;
    int row0 = blockIdx.x * 128;

    const float4* x4 = (const float4*)x;
    #pragma unroll
    for (int i = 0; i < 16; i++) {
        int idx = t + i * 256;
        int r = idx >> 5, c = idx & 31;
        float4 v = make_float4(0.f, 0.f, 0.f, 0.f);
        if (row0 + r < n) v = x4[(size_t)(row0 + r) * 32 + c];
        st4h(&As[r * 136 + c * 4], v);
    }
    const float4* W4 = (const float4*)W;
    #pragma unroll
    for (int i = 0; i < 16; i++) {
        int idx = t + i * 256;
        int r = idx >> 5, c = idx & 31;
        st4h(&Bs[r * 136 + c * 4], W4[idx]);
    }
    #pragma unroll
    for (int i = 0; i < 8; i++) {
        int idx = t + i * 256;
        int r = idx >> 7, c = idx & 127;
        Bias[r * 136 + c] = bias[c];
    }
    __syncthreads();

    int warp = t >> 5;
    int wr = warp & 3, wc = warp >> 2;

    wmma::fragment<wmma::accumulator, 16, 16, 16, float> acc[2][4];
    #pragma unroll
    for (int i = 0; i < 2; i++)
        #pragma unroll
        for (int j = 0; j < 4; j++)
            wmma::load_matrix_sync(acc[i][j], &Bias[wc * 64 + j * 16], 136,
                                   wmma::mem_row_major);

    #pragma unroll
    for (int k = 0; k < 128; k += 16) {
        wmma::fragment<wmma::matrix_a, 16, 16, 16, __half, wmma::row_major> af[2];
        wmma::fragment<wmma::matrix_b, 16, 16, 16, __half, wmma::row_major> bf[4];
        #pragma unroll
        for (int i = 0; i < 2; i++)
            wmma::load_matrix_sync(af[i], &As[(wr * 32 + i * 16) * 136 + k], 136);
        #pragma unroll
        for (int j = 0; j < 4; j++)
            wmma::load_matrix_sync(bf[j], &Bs[k * 136 + wc * 64 + j * 16], 136);
        #pragma unroll
        for (int i = 0; i < 2; i++)
            #pragma unroll
            for (int j = 0; j < 4; j++)
                wmma::mma_sync(acc[i][j], af[i], bf[j], acc[i][j]);
    }

    __syncthreads();
    #pragma unroll
    for (int i = 0; i < 2; i++)
        #pragma unroll
        for (int j = 0; j < 4; j++)
            wmma::store_matrix_sync(&Stg[(wr * 32 + i * 16) * 136 + wc * 64 + j * 16],
                                    acc[i][j], 136, wmma::mem_row_major);
    __syncthreads();
    #pragma unroll
    for (int i = 0; i < 16; i++) {
        int idx = t + i * 256;
        int r = idx >> 5, c = idx & 31;
        float4 v = *(const float4*)&Stg[r * 136 + c * 4];
        st4h((__half*)&((uint2*)g_Xhh)[(size_t)(row0 + r) * 32 + c], v);
    }
}

// ---------------- fused gates (fp16 tensor cores, spmm fused in) ----------------
// LX computed in-kernel from CSR into the A tile; then
// h = relu( sigmoid(-(Xh@Wx00 + LX@Wx01 + b0)) * tanh(Xh@Wx20 + LX@Wx21 + b2) )
// smem ~111KB -> 2 CTAs/SM
#define GAT_SMEM (67584 + 34816 + 8704)
__global__ void __launch_bounds__(256)
gates_fp16(const float* __restrict__ Wx, const float* __restrict__ bx,
           const float* __restrict__ bh, int n) {
    extern __shared__ char smc[];
    __half* As  = (__half*)smc;             // 128 x 264 half (cols 0-127 Xh, 128-255 LX)
    __half* Bs  = (__half*)(smc + 67584);   // 128 x 136 half (one weight chunk)
    float* Bias = (float*)(smc + 102400);   // 16 x 136 float
    float* Stg  = (float*)smc;              // epilogue stage 128x136 f32 (reuse As+Bs)
    int t = threadIdx.x;
    int warp = t >> 5, lane = t & 31;
    int row0 = blockIdx.x * 128;

    // phase 1: copy Xh tile (fp16) into As cols [0,128)
    #pragma unroll
    for (int i = 0; i < 16; i++) {
        int idx = t + i * 256;              // 0..4095 uint2
        int r = idx >> 5, c = idx & 31;
        uint2 v = ((const uint2*)g_Xhh)[(size_t)(row0 + r) * 32 + c];
        *(uint2*)&As[r * 264 + c * 4] = v;
    }

    // phase 2: fused SpMM — LX rows into As cols [128,256); warp per row
    for (int m = 0; m < 16; m++) {
        int r = warp * 16 + m;
        int gr = row0 + r;
        float4 acc = make_float4(0.f, 0.f, 0.f, 0.f);
        if (gr < n) {
            int beg = g_rowptr[gr], end = g_rowptr[gr + 1];
            float dv = -g_dinv[gr];
            const uint2* Xb = (const uint2*)g_Xhh;
            for (int j = beg; j < end; j++) {
                int s = g_col[j];
                float w = dv * g_dinv[s];
                uint2 val = Xb[(size_t)s * 32 + lane];
                __half2 h0 = *(__half2*)&val.x;
                __half2 h1 = *(__half2*)&val.y;
                float2 f0 = __half22float2(h0);
                float2 f1 = __half22float2(h1);
                acc.x += w * f0.x; acc.y += w * f0.y;
                acc.z += w * f1.x; acc.w += w * f1.y;
            }
        }
        st4h(&As[r * 264 + 128 + lane * 4], acc);
    }

    int wr = warp & 3, wc = warp >> 2;

    wmma::fragment<wmma::accumulator, 16, 16, 16, float> acc_z[2][4];
    wmma::fragment<wmma::accumulator, 16, 16, 16, float> acc_h[2][4];

    #pragma unroll
    for (int g = 0; g < 2; g++) {
        int g3 = (g == 0) ? 0 : 2;
        __syncthreads();   // A tile ready (g=0) / previous gate done with Bs+Bias
        // bias tile: bx[g3] + bh[g3] replicated over 16 rows
        #pragma unroll
        for (int i = 0; i < 8; i++) {
            int idx = t + i * 256;
            int r = idx >> 7, c = idx & 127;
            Bias[r * 136 + c] = bx[g3 * 128 + c] + bh[g3 * 128 + c];
        }
        // weight chunk 0: Wx[g3][0] (fp32 -> fp16)
        {
            const float4* B4 = (const float4*)(Wx + (size_t)(g3 * 2) * 16384);
            #pragma unroll
            for (int i = 0; i < 16; i++) {
                int idx = t + i * 256;
                int r = idx >> 5, c = idx & 31;
                st4h(&Bs[r * 136 + c * 4], B4[idx]);
            }
        }
        __syncthreads();

        #pragma unroll
        for (int i = 0; i < 2; i++)
            #pragma unroll
            for (int j = 0; j < 4; j++) {
                if (g == 0)
                    wmma::load_matrix_sync(acc_z[i][j], &Bias[wc * 64 + j * 16], 136,
                                           wmma::mem_row_major);
                else
                    wmma::load_matrix_sync(acc_h[i][j], &Bias[wc * 64 + j * 16], 136,
                                           wmma::mem_row_major);
            }

        #pragma unroll
        for (int c2 = 0; c2 < 2; c2++) {
            if (c2 == 1) {
                __syncthreads();
                const float4* B4b = (const float4*)(Wx + (size_t)(g3 * 2 + 1) * 16384);
                #pragma unroll
                for (int i = 0; i < 16; i++) {
                    int idx = t + i * 256;
                    int r = idx >> 5, c = idx & 31;
                    st4h(&Bs[r * 136 + c * 4], B4b[idx]);
                }
                __syncthreads();
            }
            #pragma unroll
            for (int k = 0; k < 128; k += 16) {
                wmma::fragment<wmma::matrix_a, 16, 16, 16, __half, wmma::row_major> af[2];
                wmma::fragment<wmma::matrix_b, 16, 16, 16, __half, wmma::row_major> bf[4];
                #pragma unroll
                for (int i = 0; i < 2; i++)
                    wmma::load_matrix_sync(af[i],
                        &As[(wr * 32 + i * 16) * 264 + c2 * 128 + k], 264);
                #pragma unroll
                for (int j = 0; j < 4; j++)
                    wmma::load_matrix_sync(bf[j], &Bs[k * 136 + wc * 64 + j * 16], 136);
                #pragma unroll
                for (int i = 0; i < 2; i++)
                    #pragma unroll
                    for (int j = 0; j < 4; j++) {
                        if (g == 0)
                            wmma::mma_sync(acc_z[i][j], af[i], bf[j], acc_z[i][j]);
                        else
                            wmma::mma_sync(acc_h[i][j], af[i], bf[j], acc_h[i][j]);
                    }
            }
        }

        if (g == 0) {
            // znr = 1 - sigmoid(zpre) = 1/(1+exp(zpre))
            #pragma unroll
            for (int i = 0; i < 2; i++)
                #pragma unroll
                for (int j = 0; j < 4; j++)
                    #pragma unroll
                    for (int e = 0; e < acc_z[i][j].num_elements; e++)
                        acc_z[i][j].x[e] = 1.0f / (1.0f + __expf(acc_z[i][j].x[e]));
        }
    }

    // h = relu(znr * tanh(hpre)); stage fp32 in smem, emit fp16
    #pragma unroll
    for (int i = 0; i < 2; i++)
        #pragma unroll
        for (int j = 0; j < 4; j++)
            #pragma unroll
            for (int e = 0; e < acc_h[i][j].num_elements; e++) {
                float ht = tanhf(acc_h[i][j].x[e]);
                acc_h[i][j].x[e] = fmaxf(acc_z[i][j].x[e] * ht, 0.0f);
            }
    __syncthreads();
    #pragma unroll
    for (int i = 0; i < 2; i++)
        #pragma unroll
        for (int j = 0; j < 4; j++)
            wmma::store_matrix_sync(&Stg[(wr * 32 + i * 16) * 136 + wc * 64 + j * 16],
                                    acc_h[i][j], 136, wmma::mem_row_major);
    __syncthreads();
    #pragma unroll
    for (int i = 0; i < 16; i++) {
        int idx = t + i * 256;
        int r = idx >> 5, c = idx & 31;
        float4 v = *(const float4*)&Stg[r * 136 + c * 4];
        st4h((__half*)&((uint2*)g_hh)[(size_t)(row0 + r) * 32 + c], v);
    }
}

// ---------------- decoder: out[e] = dot(h[s]*h[d], pw) + pb (fp16 h) -----------
__global__ void decoder_kernel(const void* __restrict__ eli,
                               const float* __restrict__ post_w,
                               const float* __restrict__ post_b,
                               float* __restrict__ out, int EL, int n_nodes) {
    __shared__ int sh64;
    if (threadIdx.x == 0) sh64 = detect64(eli, n_nodes);
    __syncthreads();
    int is64 = sh64;
    int gw = (blockIdx.x * blockDim.x + threadIdx.x) >> 5;
    int lane = threadIdx.x & 31;
    int nw = (gridDim.x * blockDim.x) >> 5;
    // folded decoder weights for this lane's 4 features
    float4 w0 = ((const float4*)post_w)[lane * 2];
    float4 w1 = ((const float4*)post_w)[lane * 2 + 1];
    float pw0 = w0.x + w0.y, pw1 = w0.z + w0.w;
    float pw2 = w1.x + w1.y, pw3 = w1.z + w1.w;
    float pb = post_b[0] + post_b[1];
    const uint2* H = (const uint2*)g_hh;
    for (int e = gw; e < EL; e += nw) {
        long long s = ld_idx(eli, e, is64);
        long long d = ld_idx(eli, (long long)EL + e, is64);
        uint2 av = H[(size_t)s * 32 + lane];
        uint2 bv = H[(size_t)d * 32 + lane];
        float2 a0 = __half22float2(*(__half2*)&av.x);
        float2 a1 = __half22float2(*(__half2*)&av.y);
        float2 b0 = __half22float2(*(__half2*)&bv.x);
        float2 b1 = __half22float2(*(__half2*)&bv.y);
        float acc = a0.x * b0.x * pw0 + a0.y * b0.y * pw1
                  + a1.x * b1.x * pw2 + a1.y * b1.y * pw3;
        #pragma unroll
        for (int o = 16; o > 0; o >>= 1) acc += __shfl_xor_sync(0xFFFFFFFFu, acc, o);
        if (lane == 0) out[e] = acc + pb;
    }
}

// ---------------- launch ----------------
extern "C" void kernel_launch(void* const* d_in, const int* in_sizes, int n_in,
                              void* d_out, int out_size) {
    const float* x      = (const float*)d_in[0];
    const void*  ei     = d_in[1];
    const void*  eli    = d_in[2];
    const float* pre_w  = (const float*)d_in[3];
    const float* pre_b  = (const float*)d_in[4];
    const float* Wx     = (const float*)d_in[5];
    const float* bx     = (const float*)d_in[6];
    const float* Wh     = (const float*)d_in[7];  (void)Wh;  // H0=0 -> only biases matter
    const float* bh     = (const float*)d_in[8];
    const float* post_w = (const float*)d_in[9];
    const float* post_b = (const float*)d_in[10];
    float* out = (float*)d_out;

    int N    = in_sizes[0] / HD;
    int E    = in_sizes[1] / 2;
    int EL   = in_sizes[2] / 2;
    int npad = ((N + 127) / 128) * 128;
    int nb   = (N + 1023) / 1024;

    // fork: gemm_pre (feature path) runs concurrently with the edge path
    cudaStream_t s2;
    cudaStreamCreateWithFlags(&s2, cudaStreamNonBlocking);
    cudaEvent_t evA, evB;
    cudaEventCreateWithFlags(&evA, cudaEventDisableTiming);
    cudaEventCreateWithFlags(&evB, cudaEventDisableTiming);

    cudaEventRecord(evA, 0);
    cudaStreamWaitEvent(s2, evA, 0);
    cudaFuncSetAttribute(gemm_pre_fp16,
                         cudaFuncAttributeMaxDynamicSharedMemorySize, 100 * 1024);
    gemm_pre_fp16<<<npad / 128, 256, PRE_SMEM, s2>>>(x, pre_w, pre_b, N);
    cudaEventRecord(evB, s2);

    // edge path on the capture stream
    void* p_ints = nullptr;
    cudaGetSymbolAddress(&p_ints, g_ints);
    cudaMemsetAsync(p_ints, 0, (size_t)(2 * NMAX + 64) * sizeof(int));

    hist_kernel<<<1024, 256>>>(ei, E, N);
    scan_fused<<<nb, 1024>>>(N);
    fill_kernel<<<1024, 256>>>(ei, E, N);

    // join: gates needs CSR+dinv (edge path) and Xh fp16 (feature path)
    cudaStreamWaitEvent(0, evB, 0);

    cudaFuncSetAttribute(gates_fp16,
                         cudaFuncAttributeMaxDynamicSharedMemorySize, 120 * 1024);
    gates_fp16<<<npad / 128, 256, GAT_SMEM>>>(Wx, bx, bh, N);

    decoder_kernel<<<(EL + 7) / 8, 256>>>(eli, post_w, post_b, out, EL, N);
}